// round 3
// baseline (speedup 1.0000x reference)
#include <cuda_runtime.h>
#include <math.h>

#define B_  4
#define S_  4096
#define D_  64
#define BQ  128
#define BK  128
#define QT_PER_B   32          /* S/BQ */
#define UNITS_PER_B 528        /* 32*33/2 */
#define NUNITS     2112        /* 4 * 528 */

/* strides (floats); all row strides are multiples of 4 floats (16B) */
#define QT_STRIDE (BQ + 4)     /* 132 -> 528B, 16B aligned */
#define KT_STRIDE (BK + 4)     /* 132 */
#define VS_STRIDE (D_ + 4)     /* 68  -> 272B, 16B aligned */
#define ET_STRIDE (BQ + 4)     /* 132 */

/* Et (128 x 132 = 16896 floats) exactly overlays Qt+Kt (2 x 64 x 132) */
#define SMEM_FLOATS (64*QT_STRIDE + 64*KT_STRIDE + BK*VS_STRIDE)
#define SMEM_BYTES  (SMEM_FLOATS * 4)          /* 102,400 B -> 2 CTAs/SM */

/* scratch */
__device__ float g_Lp[(size_t)NUNITS * 128];
__device__ float g_Op[(size_t)NUNITS * 128 * 64];
__device__ float g_invL[B_ * S_];

typedef unsigned long long ull;

#define FMA2(acc, a, b) \
    asm("fma.rn.f32x2 %0, %1, %2, %0;" : "+l"(acc) : "l"(a), "l"(b))
#define PACK2(d, lo, hi) \
    asm("mov.b64 %0, {%1, %2};" : "=l"(d) : "f"(lo), "f"(hi))
#define UNPACK2(lo, hi, v) \
    asm("mov.b64 {%0, %1}, %2;" : "=f"(lo), "=f"(hi) : "l"(v))

__device__ __forceinline__ float fast_exp(float x) {
    /* exp(x) = 2^(x*log2e); FFMA-only (no MUFU). */
    float t = x * 1.4426950408889634f;
    float r = t + 12582912.0f;
    int   n = __float_as_int(r) - 0x4B400000;
    float f = t - (r - 12582912.0f);
    float p = 1.3333558e-3f;
    p = fmaf(p, f, 9.6181291e-3f);
    p = fmaf(p, f, 5.5504109e-2f);
    p = fmaf(p, f, 2.4022651e-1f);
    p = fmaf(p, f, 6.9314718e-1f);
    p = fmaf(p, f, 1.0f);
    return __int_as_float(__float_as_int(p) + (n << 23));
}

/* ------------------------------------------------------------------ */
/* Kernel A: one (q-tile, k-tile) 128x128 unit per block.             */
/* f32x2 packed-FMA GEMMs; Et aliases Qt/Kt so 2 CTAs fit per SM.     */
/* ------------------------------------------------------------------ */
__global__ void __launch_bounds__(256, 2)
attn_tiles(const float* __restrict__ Q, const float* __restrict__ K,
           const float* __restrict__ V, float* __restrict__ outW,
           int writeW)
{
    extern __shared__ float sm[];
    float* Qt = sm;                          /* [64][132]  Qt[d][i]  */
    float* Kt = Qt + 64 * QT_STRIDE;         /* [64][132]  Kt[d][k]  */
    float* Et = sm;                          /* [128][132] aliases Qt+Kt */
    float* Vs = Kt + 64 * KT_STRIDE;         /* [128][68]  Vs[k][d]  */

    const int b = blockIdx.y;
    const int x = blockIdx.x;
    int qt = (int)((sqrtf(8.0f * (float)x + 1.0f) - 1.0f) * 0.5f);
    while ((qt + 1) * (qt + 2) / 2 <= x) qt++;
    while (qt * (qt + 1) / 2 > x) qt--;
    const int kt   = x - qt * (qt + 1) / 2;
    const int unit = b * UNITS_PER_B + x;

    const int tx  = threadIdx.x;   /* 0..15 */
    const int ty  = threadIdx.y;   /* 0..15 */
    const int tid = ty * 16 + tx;

    const float* Qb = Q + ((size_t)b * S_ + (size_t)qt * BQ) * D_;
    const float* Kb = K + ((size_t)b * S_ + (size_t)kt * BK) * D_;
    const float* Vb = V + ((size_t)b * S_ + (size_t)kt * BK) * D_;

    for (int e = tid; e < BQ * D_; e += 256) {
        int i = e >> 6, d = e & 63;
        Qt[d * QT_STRIDE + i] = Qb[e];
        Kt[d * KT_STRIDE + i] = Kb[e];
        Vs[i * VS_STRIDE + d] = Vb[e];
    }
    __syncthreads();

    /* ---- S = Q K^T, packed f32x2: acc2[qhalf][qrow][khalf][kpair] ---- */
    ull acc2[2][4][2][2];
#pragma unroll
    for (int a0 = 0; a0 < 2; a0++)
#pragma unroll
        for (int a1 = 0; a1 < 4; a1++)
#pragma unroll
            for (int a2 = 0; a2 < 2; a2++)
#pragma unroll
                for (int a3 = 0; a3 < 2; a3++) acc2[a0][a1][a2][a3] = 0ULL;

#pragma unroll 2
    for (int d = 0; d < 64; d++) {
        const float* qrow = Qt + d * QT_STRIDE;
        const float* krow = Kt + d * KT_STRIDE;
        float4 q0 = *(const float4*)(qrow + 4 * ty);
        float4 q1 = *(const float4*)(qrow + 64 + 4 * ty);
        ulonglong2 k0 = *(const ulonglong2*)(krow + 4 * tx);
        ulonglong2 k1 = *(const ulonglong2*)(krow + 64 + 4 * tx);
        ull kp[2][2] = {{k0.x, k0.y}, {k1.x, k1.y}};
        float qs[2][4] = {{q0.x, q0.y, q0.z, q0.w}, {q1.x, q1.y, q1.z, q1.w}};
        ull qq[2][4];
#pragma unroll
        for (int rr = 0; rr < 2; rr++)
#pragma unroll
            for (int r = 0; r < 4; r++)
                PACK2(qq[rr][r], qs[rr][r], qs[rr][r]);
#pragma unroll
        for (int rr = 0; rr < 2; rr++)
#pragma unroll
            for (int r = 0; r < 4; r++)
#pragma unroll
                for (int cc = 0; cc < 2; cc++)
#pragma unroll
                    for (int cp = 0; cp < 2; cp++)
                        FMA2(acc2[rr][r][cc][cp], qq[rr][r], kp[cc][cp]);
    }

    /* all Qt/Kt reads done before Et (aliased) is written */
    __syncthreads();

    /* ---- mask + exp + row sums + stores, one q-half at a time ---- */
    const bool diag = (qt == kt);
#pragma unroll
    for (int rr = 0; rr < 2; rr++) {
        float a[4][2][4];   /* [r][cc][c] */
#pragma unroll
        for (int r = 0; r < 4; r++)
#pragma unroll
            for (int cc = 0; cc < 2; cc++)
#pragma unroll
                for (int cp = 0; cp < 2; cp++)
                    UNPACK2(a[r][cc][2 * cp], a[r][cc][2 * cp + 1],
                            acc2[rr][r][cc][cp]);

#pragma unroll
        for (int r = 0; r < 4; r++) {
            const int i = rr * 64 + 4 * ty + r;
            float rs = 0.0f;
#pragma unroll
            for (int cc = 0; cc < 2; cc++) {
#pragma unroll
                for (int c = 0; c < 4; c++) {
                    const int j = cc * 64 + 4 * tx + c;
                    float s = a[r][cc][c] * 0.125f;
                    float e = (diag && (j > i)) ? 0.0f : fast_exp(s);
                    a[r][cc][c] = e;
                    rs += e;
                }
            }
            /* reduce across tx (lane bits 0..3) */
            rs += __shfl_xor_sync(0xffffffffu, rs, 1);
            rs += __shfl_xor_sync(0xffffffffu, rs, 2);
            rs += __shfl_xor_sync(0xffffffffu, rs, 4);
            rs += __shfl_xor_sync(0xffffffffu, rs, 8);
            if (tx == 0)
                g_Lp[(size_t)unit * 128 + i] = rs;

            float* grow = outW + ((size_t)(b * S_ + qt * BQ + i)) * S_
                               + (size_t)kt * BK;
#pragma unroll
            for (int cc = 0; cc < 2; cc++) {
                if (writeW) {
                    float4 w;
                    w.x = a[r][cc][0]; w.y = a[r][cc][1];
                    w.z = a[r][cc][2]; w.w = a[r][cc][3];
                    *(float4*)(grow + cc * 64 + 4 * tx) = w;
                }
#pragma unroll
                for (int c = 0; c < 4; c++)
                    Et[(cc * 64 + 4 * tx + c) * ET_STRIDE + i] = a[r][cc][c];
            }
        }
    }
    __syncthreads();

    /* ---- partial O = E @ V, packed f32x2: o2[rr][r][dpair] ---- */
    ull o2[2][4][2];
#pragma unroll
    for (int a0 = 0; a0 < 2; a0++)
#pragma unroll
        for (int a1 = 0; a1 < 4; a1++)
#pragma unroll
            for (int a2 = 0; a2 < 2; a2++) o2[a0][a1][a2] = 0ULL;

#pragma unroll 2
    for (int j = 0; j < BK; j++) {
        const float* erow = Et + j * ET_STRIDE;
        float4 e0 = *(const float4*)(erow + 4 * ty);
        float4 e1 = *(const float4*)(erow + 64 + 4 * ty);
        ulonglong2 vv = *(const ulonglong2*)(Vs + j * VS_STRIDE + 4 * tx);
        ull vp[2] = {vv.x, vv.y};
        float es[2][4] = {{e0.x, e0.y, e0.z, e0.w}, {e1.x, e1.y, e1.z, e1.w}};
        ull ee[2][4];
#pragma unroll
        for (int rr = 0; rr < 2; rr++)
#pragma unroll
            for (int r = 0; r < 4; r++)
                PACK2(ee[rr][r], es[rr][r], es[rr][r]);
#pragma unroll
        for (int rr = 0; rr < 2; rr++)
#pragma unroll
            for (int r = 0; r < 4; r++)
#pragma unroll
                for (int cp = 0; cp < 2; cp++)
                    FMA2(o2[rr][r][cp], ee[rr][r], vp[cp]);
    }

    float* Ob = g_Op + (size_t)unit * (128 * 64);
#pragma unroll
    for (int rr = 0; rr < 2; rr++)
#pragma unroll
        for (int r = 0; r < 4; r++) {
            const int i = rr * 64 + 4 * ty + r;
            float4 w;
            UNPACK2(w.x, w.y, o2[rr][r][0]);
            UNPACK2(w.z, w.w, o2[rr][r][1]);
            *(float4*)(Ob + i * 64 + 4 * tx) = w;
        }
}

/* ---------------- Kernel B1: invL per row ---------------- */
__global__ void __launch_bounds__(256)
reduce_l()
{
    int t = blockIdx.x * 256 + threadIdx.x;
    if (t >= B_ * S_) return;
    int b = t >> 12, q = t & (S_ - 1);
    int qt = q >> 7, i = q & 127;
    int tri = qt * (qt + 1) / 2;
    float s = 0.0f;
    for (int kt = 0; kt <= qt; kt++)
        s += g_Lp[((size_t)(b * UNITS_PER_B + tri + kt)) * 128 + i];
    g_invL[t] = 1.0f / s;
}

/* ---------------- Kernel B2: O = (sum of partials) * invL ---------------- */
__global__ void __launch_bounds__(256)
reduce_o(float* __restrict__ outV)
{
    int t = blockIdx.x * 256 + threadIdx.x;
    if (t >= B_ * S_ * (D_ / 4)) return;
    int d4 = t & 15;
    int q  = (t >> 4) & (S_ - 1);
    int b  = t >> 16;
    int qt = q >> 7, i = q & 127;
    int tri = qt * (qt + 1) / 2;
    float ax = 0.f, ay = 0.f, az = 0.f, aw = 0.f;
    for (int kt = 0; kt <= qt; kt++) {
        const float4 v = *(const float4*)(g_Op +
            ((size_t)(b * UNITS_PER_B + tri + kt) * 128 + i) * 64 + d4 * 4);
        ax += v.x; ay += v.y; az += v.z; aw += v.w;
    }
    float inv = g_invL[b * S_ + q];
    float4 r; r.x = ax * inv; r.y = ay * inv; r.z = az * inv; r.w = aw * inv;
    *(float4*)(outV + ((size_t)(b * S_ + q)) * D_ + d4 * 4) = r;
}

/* ---------------- Kernel C: normalize weights + zero upper tiles -------- */
__global__ void __launch_bounds__(256)
norm_w(float* __restrict__ outW)
{
    size_t t = (size_t)blockIdx.x * 256 + threadIdx.x;   /* float4 index */
    int kq = (int)(t & 1023);
    int q  = (int)((t >> 10) & (S_ - 1));
    int b  = (int)(t >> 22);
    float4* p = (float4*)outW + t;
    int k = kq * 4;
    if ((k >> 7) > (q >> 7)) {
        float4 z; z.x = z.y = z.z = z.w = 0.0f;
        *p = z;
    } else {
        float inv = g_invL[b * S_ + q];
        float4 v = *p;
        v.x *= inv; v.y *= inv; v.z *= inv; v.w *= inv;
        *p = v;
    }
}

/* ------------------------------------------------------------------ */
extern "C" void kernel_launch(void* const* d_in, const int* in_sizes, int n_in,
                              void* d_out, int out_size)
{
    const float* Q = (const float*)d_in[0];
    const float* K = (const float*)d_in[1];
    const float* V = (const float*)d_in[2];

    const long long VE = (long long)B_ * S_ * D_;       /* 1,048,576  */
    const long long WE = (long long)B_ * S_ * S_;       /* 67,108,864 */

    float* outVec = nullptr;
    float* outW   = nullptr;
    int writeW = 0;
    if ((long long)out_size == VE + WE) {
        outVec = (float*)d_out;
        outW   = (float*)d_out + VE;
        writeW = 1;
    } else if ((long long)out_size == WE) {
        outW   = (float*)d_out;
        writeW = 1;
    } else {
        outVec = (float*)d_out;
    }
    float* wPtr = writeW ? outW : (float*)d_out;

    cudaFuncSetAttribute(attn_tiles, cudaFuncAttributeMaxDynamicSharedMemorySize,
                         SMEM_BYTES);

    dim3 gA(UNITS_PER_B, B_);
    dim3 bA(16, 16);
    attn_tiles<<<gA, bA, SMEM_BYTES>>>(Q, K, V, wPtr, writeW);

    reduce_l<<<(B_ * S_ + 255) / 256, 256>>>();

    if (outVec)
        reduce_o<<<(B_ * S_ * (D_ / 4) + 255) / 256, 256>>>(outVec);

    if (writeW) {
        long long nf4 = WE / 4;
        norm_w<<<(unsigned)(nf4 / 256), 256>>>(outW);
    }
}

// round 5
// speedup vs baseline: 1.6137x; 1.6137x over previous
#include <cuda_runtime.h>
#include <cuda_bf16.h>
#include <cstdint>
#include <math.h>

#define B_  4
#define S_  4096
#define D_  64
#define BQ  128
#define BK  128
#define QT_PER_B   32
#define UNITS_PER_B 528
#define NUNITS     2112

/* ---------------- scratch ---------------- */
__device__ float g_Lp[(size_t)NUNITS * 128];
__device__ float g_Op[(size_t)NUNITS * 128 * 64];
__device__ float g_invL[B_ * S_];

/* ---------------- SMEM map (bytes) ----------------
   Q/K tiles: [128 rows][72 bf16] (stride 72 -> (4r+tg)%32 all-distinct banks)
   Vt tiles : [64 rows d][136 bf16] (k-major transposed V)
   E tiles  : [128 rows][136 bf16], aliases Q/K region                     */
#define QK_STRIDE 72
#define EV_STRIDE 136
#define SM_RSUM   0                        /* 128*2 floats = 1024 B */
#define SM_QHI    1024
#define SM_QLO    (SM_QHI + 18432)
#define SM_KHI    (SM_QLO + 18432)
#define SM_KLO    (SM_KHI + 18432)
#define SM_VTHI   (SM_KLO + 18432)         /* 64*136*2 = 17408 */
#define SM_VTLO   (SM_VTHI + 17408)
#define SM_EHI    SM_QHI                   /* 128*136*2 = 34816, alias */
#define SM_ELO    (SM_QHI + 34816)
#define SMEM_TOTAL (SM_VTLO + 17408)       /* 109568 B -> 2 CTAs/SM */

#define MMA16816(c, a, b0, b1) \
    asm volatile("mma.sync.aligned.m16n8k16.row.col.f32.bf16.bf16.f32 " \
        "{%0,%1,%2,%3}, {%4,%5,%6,%7}, {%8,%9}, {%0,%1,%2,%3};"         \
        : "+f"((c)[0]), "+f"((c)[1]), "+f"((c)[2]), "+f"((c)[3])        \
        : "r"((a)[0]), "r"((a)[1]), "r"((a)[2]), "r"((a)[3]),           \
          "r"(b0), "r"(b1))

__device__ __forceinline__ float fast_exp(float x) {
    float t = x * 1.4426950408889634f;
    float r = t + 12582912.0f;
    int   n = __float_as_int(r) - 0x4B400000;
    float f = t - (r - 12582912.0f);
    float p = 1.3333558e-3f;
    p = fmaf(p, f, 9.6181291e-3f);
    p = fmaf(p, f, 5.5504109e-2f);
    p = fmaf(p, f, 2.4022651e-1f);
    p = fmaf(p, f, 6.9314718e-1f);
    p = fmaf(p, f, 1.0f);
    return __int_as_float(__float_as_int(p) + (n << 23));
}

/* ------------------------------------------------------------------ */
/* Kernel A: one (qt, kt) 128x128 unit per CTA; HMMA bf16 3-way split */
/* ------------------------------------------------------------------ */
__global__ void __launch_bounds__(256, 2)
attn_tiles(const float* __restrict__ Q, const float* __restrict__ K,
           const float* __restrict__ V, float* __restrict__ outW,
           int writeW)
{
    extern __shared__ char smx[];

    const int tid = threadIdx.x;
    const int wid = tid >> 5;
    const int lid = tid & 31;
    const int g   = lid >> 2;   /* group id (row within frag) */
    const int tg  = lid & 3;    /* thread in group (col pair)  */
    const int wr  = wid & 3;    /* warp row block: 32 rows     */
    const int wc  = wid >> 2;   /* warp col block              */

    const int b = blockIdx.y;
    const int x = blockIdx.x;
    int qt = (int)((sqrtf(8.0f * (float)x + 1.0f) - 1.0f) * 0.5f);
    while ((qt + 1) * (qt + 2) / 2 <= x) qt++;
    while (qt * (qt + 1) / 2 > x) qt--;
    const int kt   = x - qt * (qt + 1) / 2;
    const int unit = b * UNITS_PER_B + x;
    const bool diag = (qt == kt);

    const float2* Qb = (const float2*)(Q + ((size_t)b * S_ + (size_t)qt * BQ) * D_);
    const float2* Kb = (const float2*)(K + ((size_t)b * S_ + (size_t)kt * BK) * D_);
    const float2* Vb = (const float2*)(V + ((size_t)b * S_ + (size_t)kt * BK) * D_);

    /* ---- load Q,K: split hi/lo bf16, row-major stride 72 ---- */
    for (int idx = tid; idx < 4096; idx += 256) {
        const int row = idx >> 5, cp = idx & 31;   /* cp: float2 within row */
        {
            float2 v = Qb[idx];
            __nv_bfloat162 h, l;
            h.x = __float2bfloat16(v.x); h.y = __float2bfloat16(v.y);
            l.x = __float2bfloat16(v.x - __bfloat162float(h.x));
            l.y = __float2bfloat16(v.y - __bfloat162float(h.y));
            *(__nv_bfloat162*)(smx + SM_QHI + (row * QK_STRIDE + 2 * cp) * 2) = h;
            *(__nv_bfloat162*)(smx + SM_QLO + (row * QK_STRIDE + 2 * cp) * 2) = l;
        }
        {
            float2 v = Kb[idx];
            __nv_bfloat162 h, l;
            h.x = __float2bfloat16(v.x); h.y = __float2bfloat16(v.y);
            l.x = __float2bfloat16(v.x - __bfloat162float(h.x));
            l.y = __float2bfloat16(v.y - __bfloat162float(h.y));
            *(__nv_bfloat162*)(smx + SM_KHI + (row * QK_STRIDE + 2 * cp) * 2) = h;
            *(__nv_bfloat162*)(smx + SM_KLO + (row * QK_STRIDE + 2 * cp) * 2) = l;
        }
    }
    /* ---- V transpose -> Vt[d][k], stride 136 (coalesced gmem reads) ---- */
    for (int idx = tid; idx < 4096; idx += 256) {
        const int k = idx >> 5, dp = idx & 31;
        float2 v = Vb[idx];
#pragma unroll
        for (int s = 0; s < 2; s++) {
            const int d = 2 * dp + s;
            const float xv = s ? v.y : v.x;
            __nv_bfloat16 h = __float2bfloat16(xv);
            __nv_bfloat16 l = __float2bfloat16(xv - __bfloat162float(h));
            *(__nv_bfloat16*)(smx + SM_VTHI + (d * EV_STRIDE + k) * 2) = h;
            *(__nv_bfloat16*)(smx + SM_VTLO + (d * EV_STRIDE + k) * 2) = l;
        }
    }
    __syncthreads();

    /* ================= QK^T: warp tile 32 x 64 ================= */
    /* c[t][j][4]: t = 16-row tile, j = 8-col tile                  */
    float c[2][8][4];
#pragma unroll
    for (int t = 0; t < 2; t++)
#pragma unroll
        for (int j = 0; j < 8; j++)
#pragma unroll
            for (int r = 0; r < 4; r++) c[t][j][r] = 0.0f;

#pragma unroll
    for (int p = 0; p < 3; p++) {
        const char* Ab = smx + ((p == 2) ? SM_QLO : SM_QHI);
        const char* Bb = smx + ((p == 1) ? SM_KLO : SM_KHI);
#pragma unroll
        for (int ks = 0; ks < 4; ks++) {
            uint32_t a[2][4];
#pragma unroll
            for (int t = 0; t < 2; t++) {
                const int base = (32 * wr + 16 * t + g) * QK_STRIDE + 16 * ks + 2 * tg;
                a[t][0] = *(const uint32_t*)(Ab + 2 * base);
                a[t][1] = *(const uint32_t*)(Ab + 2 * (base + 8 * QK_STRIDE));
                a[t][2] = *(const uint32_t*)(Ab + 2 * (base + 8));
                a[t][3] = *(const uint32_t*)(Ab + 2 * (base + 8 * QK_STRIDE + 8));
            }
#pragma unroll
            for (int j = 0; j < 8; j++) {
                const int cb = (64 * wc + 8 * j + g) * QK_STRIDE + 16 * ks + 2 * tg;
                uint32_t b0 = *(const uint32_t*)(Bb + 2 * cb);
                uint32_t b1 = *(const uint32_t*)(Bb + 2 * (cb + 8));
                MMA16816(c[0][j], a[0], b0, b1);
                MMA16816(c[1][j], a[1], b0, b1);
            }
        }
    }
    __syncthreads();   /* all Q/K smem reads done; E may overwrite */

    /* ============ epilogue: mask+exp, W store, E split, row sums ============ */
    float rs[2][2] = {{0.0f, 0.0f}, {0.0f, 0.0f}};
#pragma unroll
    for (int t = 0; t < 2; t++) {
#pragma unroll
        for (int u = 0; u < 2; u++) {
            const int row = 32 * wr + 16 * t + 8 * u + g;
            float* grow = outW + ((size_t)(b * S_ + qt * BQ + row)) * S_
                               + (size_t)kt * BK;
#pragma unroll
            for (int j = 0; j < 8; j++) {
                const int cb = 64 * wc + 8 * j + 2 * tg;
                float s0 = c[t][j][2 * u]     * 0.125f;
                float s1 = c[t][j][2 * u + 1] * 0.125f;
                float e0 = (diag && (cb     > row)) ? 0.0f : fast_exp(s0);
                float e1 = (diag && (cb + 1 > row)) ? 0.0f : fast_exp(s1);
                rs[t][u] += e0 + e1;
                if (writeW) {
                    float2 w; w.x = e0; w.y = e1;
                    *(float2*)(grow + cb) = w;
                }
                __nv_bfloat162 h, l;
                h.x = __float2bfloat16(e0); h.y = __float2bfloat16(e1);
                l.x = __float2bfloat16(e0 - __bfloat162float(h.x));
                l.y = __float2bfloat16(e1 - __bfloat162float(h.y));
                *(__nv_bfloat162*)(smx + SM_EHI + (row * EV_STRIDE + cb) * 2) = h;
                *(__nv_bfloat162*)(smx + SM_ELO + (row * EV_STRIDE + cb) * 2) = l;
            }
        }
    }
    /* reduce row sums across the 4 tg lanes (same rows) */
#pragma unroll
    for (int t = 0; t < 2; t++)
#pragma unroll
        for (int u = 0; u < 2; u++) {
            float v = rs[t][u];
            v += __shfl_xor_sync(0xffffffffu, v, 1);
            v += __shfl_xor_sync(0xffffffffu, v, 2);
            if (tg == 0) {
                const int row = 32 * wr + 16 * t + 8 * u + g;
                ((float*)(smx + SM_RSUM))[row * 2 + wc] = v;
            }
        }
    __syncthreads();

    if (tid < 128) {
        const float* r = (const float*)(smx + SM_RSUM);
        g_Lp[(size_t)unit * 128 + tid] = r[2 * tid] + r[2 * tid + 1];
    }

    /* ================= O = E @ V: warp tile 32 x 32 ================= */
    float o[2][4][4];
#pragma unroll
    for (int t = 0; t < 2; t++)
#pragma unroll
        for (int j = 0; j < 4; j++)
#pragma unroll
            for (int r = 0; r < 4; r++) o[t][j][r] = 0.0f;

#pragma unroll
    for (int p = 0; p < 3; p++) {
        const char* Ab = smx + ((p == 2) ? SM_ELO : SM_EHI);
        const char* Bb = smx + ((p == 1) ? SM_VTLO : SM_VTHI);
#pragma unroll
        for (int ks = 0; ks < 8; ks++) {
            uint32_t a[2][4];
#pragma unroll
            for (int t = 0; t < 2; t++) {
                const int base = (32 * wr + 16 * t + g) * EV_STRIDE + 16 * ks + 2 * tg;
                a[t][0] = *(const uint32_t*)(Ab + 2 * base);
                a[t][1] = *(const uint32_t*)(Ab + 2 * (base + 8 * EV_STRIDE));
                a[t][2] = *(const uint32_t*)(Ab + 2 * (base + 8));
                a[t][3] = *(const uint32_t*)(Ab + 2 * (base + 8 * EV_STRIDE + 8));
            }
#pragma unroll
            for (int j = 0; j < 4; j++) {
                const int cb = (32 * wc + 8 * j + g) * EV_STRIDE + 16 * ks + 2 * tg;
                uint32_t b0 = *(const uint32_t*)(Bb + 2 * cb);
                uint32_t b1 = *(const uint32_t*)(Bb + 2 * (cb + 8));
                MMA16816(o[0][j], a[0], b0, b1);
                MMA16816(o[1][j], a[1], b0, b1);
            }
        }
    }

    /* ---- store O partials ---- */
    float* Ob = g_Op + (size_t)unit * (128 * 64);
#pragma unroll
    for (int t = 0; t < 2; t++)
#pragma unroll
        for (int u = 0; u < 2; u++) {
            const int row = 32 * wr + 16 * t + 8 * u + g;
#pragma unroll
            for (int j = 0; j < 4; j++) {
                const int cb = 32 * wc + 8 * j + 2 * tg;
                float2 w;
                w.x = o[t][j][2 * u];
                w.y = o[t][j][2 * u + 1];
                *(float2*)(Ob + (size_t)row * 64 + cb) = w;
            }
        }
}

/* ---------------- Kernel B1: invL per row ---------------- */
__global__ void __launch_bounds__(256)
reduce_l()
{
    int t = blockIdx.x * 256 + threadIdx.x;
    if (t >= B_ * S_) return;
    int b = t >> 12, q = t & (S_ - 1);
    int qt = q >> 7, i = q & 127;
    int tri = qt * (qt + 1) / 2;
    float s = 0.0f;
    for (int kt = 0; kt <= qt; kt++)
        s += g_Lp[((size_t)(b * UNITS_PER_B + tri + kt)) * 128 + i];
    g_invL[t] = 1.0f / s;
}

/* ---------------- Kernel B2: O = (sum of partials) * invL ---------------- */
__global__ void __launch_bounds__(256)
reduce_o(float* __restrict__ outV)
{
    int t = blockIdx.x * 256 + threadIdx.x;
    if (t >= B_ * S_ * (D_ / 4)) return;
    int d4 = t & 15;
    int q  = (t >> 4) & (S_ - 1);
    int b  = t >> 16;
    int qt = q >> 7, i = q & 127;
    int tri = qt * (qt + 1) / 2;
    float ax = 0.f, ay = 0.f, az = 0.f, aw = 0.f;
    for (int kt = 0; kt <= qt; kt++) {
        const float4 v = *(const float4*)(g_Op +
            ((size_t)(b * UNITS_PER_B + tri + kt) * 128 + i) * 64 + d4 * 4);
        ax += v.x; ay += v.y; az += v.z; aw += v.w;
    }
    float inv = g_invL[b * S_ + q];
    float4 r; r.x = ax * inv; r.y = ay * inv; r.z = az * inv; r.w = aw * inv;
    *(float4*)(outV + ((size_t)(b * S_ + q)) * D_ + d4 * 4) = r;
}

/* ---------------- Kernel C: normalize weights + zero upper tiles -------- */
__global__ void __launch_bounds__(256)
norm_w(float* __restrict__ outW)
{
    size_t t = (size_t)blockIdx.x * 256 + threadIdx.x;   /* float4 index */
    int kq = (int)(t & 1023);
    int q  = (int)((t >> 10) & (S_ - 1));
    int b  = (int)(t >> 22);
    float4* p = (float4*)outW + t;
    int k = kq * 4;
    if ((k >> 7) > (q >> 7)) {
        float4 z; z.x = z.y = z.z = z.w = 0.0f;
        *p = z;
    } else {
        float inv = g_invL[b * S_ + q];
        float4 v = *p;
        v.x *= inv; v.y *= inv; v.z *= inv; v.w *= inv;
        *p = v;
    }
}

/* ------------------------------------------------------------------ */
extern "C" void kernel_launch(void* const* d_in, const int* in_sizes, int n_in,
                              void* d_out, int out_size)
{
    const float* Q = (const float*)d_in[0];
    const float* K = (const float*)d_in[1];
    const float* V = (const float*)d_in[2];

    const long long VE = (long long)B_ * S_ * D_;
    const long long WE = (long long)B_ * S_ * S_;

    float* outVec = nullptr;
    float* outW   = nullptr;
    int writeW = 0;
    if ((long long)out_size == VE + WE) {
        outVec = (float*)d_out;
        outW   = (float*)d_out + VE;
        writeW = 1;
    } else if ((long long)out_size == WE) {
        outW   = (float*)d_out;
        writeW = 1;
    } else {
        outVec = (float*)d_out;
    }
    float* wPtr = writeW ? outW : (float*)d_out;

    cudaFuncSetAttribute(attn_tiles, cudaFuncAttributeMaxDynamicSharedMemorySize,
                         SMEM_TOTAL);

    dim3 gA(UNITS_PER_B, B_);
    attn_tiles<<<gA, 256, SMEM_TOTAL>>>(Q, K, V, wPtr, writeW);

    reduce_l<<<(B_ * S_ + 255) / 256, 256>>>();

    if (outVec)
        reduce_o<<<(B_ * S_ * (D_ / 4) + 255) / 256, 256>>>(outVec);

    if (writeW) {
        long long nf4 = WE / 4;
        norm_w<<<(unsigned)(nf4 / 256), 256>>>(outW);
    }
}